// round 3
// baseline (speedup 1.0000x reference)
#include <cuda_runtime.h>

// Problem shape (fixed by the bench)
#define BB 8
#define SS 2048
#define HH 2048

// Scratch (no allocations allowed)
__device__ float g_uv[BB * SS * 4];      // per-row dots: h·W[:H,0], h·W[:H,1], h·W[H:,0], h·W[H:,1]
__device__ float g_v[BB * SS];           // per-input-position weight in transform
__device__ int   g_seg_start[BB * SS];   // first input s for output row t
__device__ int   g_seg_len[BB * SS];     // number of input s for output row t
__device__ int   g_new_len[BB];

// ---------------------------------------------------------------------------
// Kernel A: 4 dot products of length H per token. One 256-thread block per row.
// ---------------------------------------------------------------------------
__global__ void __launch_bounds__(256) k_dots(const float* __restrict__ h,
                                              const float* __restrict__ W) {
    const int row = blockIdx.x;                      // b*SS + s
    const float4* hp = reinterpret_cast<const float4*>(h) + (size_t)row * (HH / 4);
    const float4* Wp = reinterpret_cast<const float4*>(W);   // W: [2H,2] row-major
    const int tid = threadIdx.x;

    float a0 = 0.f, a1 = 0.f, c0 = 0.f, c1 = 0.f;
#pragma unroll
    for (int k = 0; k < 2; k++) {
        const int q = tid + k * 256;                 // float4 index 0..511
        const float4 hv = __ldg(hp + q);
        const int j = q * 4;                         // element index (multiple of 4)
        // W rows j..j+3 for first-half weights: float4s at (2j)/4 = j/2
        const float4 wa0 = __ldg(Wp + (j >> 1));
        const float4 wa1 = __ldg(Wp + (j >> 1) + 1);
        // W rows H+j..H+j+3: float4s at (2(H+j))/4 = (H+j)/2
        const float4 wb0 = __ldg(Wp + ((HH + j) >> 1));
        const float4 wb1 = __ldg(Wp + ((HH + j) >> 1) + 1);
        a0 += hv.x * wa0.x + hv.y * wa0.z + hv.z * wa1.x + hv.w * wa1.z;
        a1 += hv.x * wa0.y + hv.y * wa0.w + hv.z * wa1.y + hv.w * wa1.w;
        c0 += hv.x * wb0.x + hv.y * wb0.z + hv.z * wb1.x + hv.w * wb1.z;
        c1 += hv.x * wb0.y + hv.y * wb0.w + hv.z * wb1.y + hv.w * wb1.w;
    }
#pragma unroll
    for (int off = 16; off > 0; off >>= 1) {
        a0 += __shfl_down_sync(0xffffffffu, a0, off);
        a1 += __shfl_down_sync(0xffffffffu, a1, off);
        c0 += __shfl_down_sync(0xffffffffu, c0, off);
        c1 += __shfl_down_sync(0xffffffffu, c1, off);
    }
    __shared__ float red[8][4];
    const int warp = tid >> 5, lane = tid & 31;
    if (lane == 0) { red[warp][0] = a0; red[warp][1] = a1; red[warp][2] = c0; red[warp][3] = c1; }
    __syncthreads();
    if (tid == 0) {
        float s0 = 0.f, s1 = 0.f, s2 = 0.f, s3 = 0.f;
#pragma unroll
        for (int w = 0; w < 8; w++) { s0 += red[w][0]; s1 += red[w][1]; s2 += red[w][2]; s3 += red[w][3]; }
        float* o = g_uv + (size_t)row * 4;
        o[0] = s0; o[1] = s1; o[2] = s2; o[3] = s3;
    }
}

// ---------------------------------------------------------------------------
// Kernel B: per-batch. logits, gumbel-softmax, mm, want, v, prefix scan of inc,
// segment map, and all small outputs. One 256-thread block per batch.
// ---------------------------------------------------------------------------
__global__ void __launch_bounds__(256) k_scan(const int* __restrict__ amask,
                                              const int* __restrict__ smask,
                                              const float* __restrict__ gum,
                                              const float* __restrict__ bias,
                                              float* __restrict__ out) {
    const int b = blockIdx.x;
    const int tid = threadIdx.x;
    const size_t base = (size_t)b * SS;

    __shared__ unsigned char want_sh[SS];
    __shared__ int r_sh[SS];
    __shared__ int part[256];
    __shared__ int cnt_sh[SS];
    __shared__ int sst_sh[SS];
    __shared__ int sh_T;

    // output layout: tuple members concatenated, all fp32
    float* out_mask    = out + (size_t)BB * SS * HH;
    float* out_special = out_mask + (size_t)BB * SS;
    float* out_counts  = out_special + (size_t)BB * SS;
    float* out_mm      = out_counts + (size_t)BB * SS;
    float* out_logits  = out_mm + (size_t)BB * SS * 2;

    // --- T = sum(attention_mask[b]) ---
    if (tid == 0) sh_T = 0;
    __syncthreads();
    {
        int local = 0;
#pragma unroll
        for (int i = 0; i < 8; i++) local += amask[base + tid * 8 + i];
        atomicAdd(&sh_T, local);
    }
    __syncthreads();
    const int T = sh_T;

    const float b0v = __ldg(bias + 0), b1v = __ldg(bias + 1);

    // --- per-position: logits, gumbel-softmax, mm, want, v ---
#pragma unroll
    for (int i = 0; i < 8; i++) {
        const int s = tid * 8 + i;
        float l0, l1;
        if (s < SS - 1) {
            const float* uvA = g_uv + (base + s) * 4;
            const float* uvB = g_uv + (base + s + 1) * 4;
            l0 = uvA[0] + uvB[2] + b0v;
            l1 = uvA[1] + uvB[3] + b1v;
        } else {                                     // zero stub row
            l0 = b0v; l1 = b1v;
        }
        out_logits[(base + s) * 2 + 0] = l0;
        out_logits[(base + s) * 2 + 1] = l1;

        const float z0 = l0 + gum[(base + s) * 2 + 0];
        const float z1 = l1 + gum[(base + s) * 2 + 1];
        const float m = fmaxf(z0, z1);
        const float e0 = expf(z0 - m), e1 = expf(z1 - m);
        const float inv = 1.f / (e0 + e1);
        const float ys0 = e0 * inv, ys1 = e1 * inv;
        const int idx1 = (ys1 > ys0) ? 1 : 0;        // argmax, ties -> 0 (matches jnp)
        float mm0 = ((idx1 == 0 ? 1.f : 0.f) - ys0) + ys0;   // straight-through, exact fp order
        float mm1 = ((idx1 == 1 ? 1.f : 0.f) - ys1) + ys1;
        if (smask[base + s]) { mm0 = 1.f; mm1 = 0.f; }
        const float mf = amask[base + s] ? 1.f : 0.f;
        mm0 *= mf; mm1 *= mf;
        out_mm[(base + s) * 2 + 0] = mm0;
        out_mm[(base + s) * 2 + 1] = mm1;

        const bool want = (mm1 > 0.5f) && (s >= 1) && (s < T - 1);
        want_sh[s] = want ? 1 : 0;
        float v = want ? mm1 : mm0;
        if (s == 0) v = 1.f;
        if (s >= T) v = 0.f;
        g_v[base + s] = v;
    }
    __syncthreads();

    // --- inc + block prefix scan -> r ---
    int incs[8];
    {
        int csum = 0;
#pragma unroll
        for (int i = 0; i < 8; i++) {
            const int s = tid * 8 + i;
            const int w = want_sh[s];
            const int wp = (s > 0) ? want_sh[s - 1] : 0;
            const int inc = (s < T && s >= 1 && !(w && wp)) ? 1 : 0;
            csum += inc;
            incs[i] = csum;                          // local inclusive
        }
        part[tid] = csum;
    }
    __syncthreads();
    for (int off = 1; off < 256; off <<= 1) {
        const int add = (tid >= off) ? part[tid - off] : 0;
        __syncthreads();
        part[tid] += add;
        __syncthreads();
    }
    {
        const int offset = (tid > 0) ? part[tid - 1] : 0;
#pragma unroll
        for (int i = 0; i < 8; i++) r_sh[tid * 8 + i] = offset + incs[i];
    }
    __syncthreads();

    // --- segment map via shared atomics ---
#pragma unroll
    for (int i = 0; i < 8; i++) { cnt_sh[tid * 8 + i] = 0; sst_sh[tid * 8 + i] = 0x7fffffff; }
    __syncthreads();
#pragma unroll
    for (int i = 0; i < 8; i++) {
        const int s = tid * 8 + i;
        if (s < T) {
            const int r = r_sh[s];
            atomicAdd(&cnt_sh[r], 1);
            atomicMin(&sst_sh[r], s);
        }
    }
    __syncthreads();

    const int nl = r_sh[SS - 1] + 1;                 // matches reference r[:, -1] + 1
#pragma unroll
    for (int i = 0; i < 8; i++) {
        const int t = tid * 8 + i;
        out_mask[base + t]    = (t < nl) ? 1.f : 0.f;
        out_special[base + t] = (t == 0 || t == nl - 1) ? 1.f : 0.f;
        out_counts[base + t]  = (float)cnt_sh[t];
        g_seg_start[base + t] = sst_sh[t];
        g_seg_len[base + t]   = cnt_sh[t];
    }
    if (tid == 0) g_new_len[b] = nl;
}

// ---------------------------------------------------------------------------
// Kernel C: merged_hidden[b,t,:] = sum over the run of v[s]*h[b,s,:].
// One 256-thread block per output row; zeros for t >= new_len.
// ---------------------------------------------------------------------------
__global__ void __launch_bounds__(256) k_merge(const float* __restrict__ h,
                                               float* __restrict__ out) {
    const int row = blockIdx.x;                      // b*SS + t
    const int b = row >> 11;                         // / SS
    const int t = row & (SS - 1);
    const int tid = threadIdx.x;

    float4 acc0 = make_float4(0.f, 0.f, 0.f, 0.f);
    float4 acc1 = make_float4(0.f, 0.f, 0.f, 0.f);

    if (t < g_new_len[b]) {
        const int s0 = g_seg_start[row];
        const int L  = g_seg_len[row];
        for (int i = 0; i < L; i++) {
            const size_t srow = (size_t)b * SS + s0 + i;
            const float w = __ldg(g_v + srow);
            const float4* hr = reinterpret_cast<const float4*>(h) + srow * (HH / 4);
            const float4 h0 = __ldg(hr + tid);
            const float4 h1 = __ldg(hr + tid + 256);
            acc0.x += w * h0.x; acc0.y += w * h0.y; acc0.z += w * h0.z; acc0.w += w * h0.w;
            acc1.x += w * h1.x; acc1.y += w * h1.y; acc1.z += w * h1.z; acc1.w += w * h1.w;
        }
    }
    float4* orow = reinterpret_cast<float4*>(out) + (size_t)row * (HH / 4);
    orow[tid] = acc0;
    orow[tid + 256] = acc1;
}

// ---------------------------------------------------------------------------
extern "C" void kernel_launch(void* const* d_in, const int* in_sizes, int n_in,
                              void* d_out, int out_size) {
    const float* h     = (const float*)d_in[0];   // [B,S,H] f32
    const int*   amask = (const int*)d_in[1];     // [B,S]   i32
    const int*   smask = (const int*)d_in[2];     // [B,S]   i32
    const float* gum   = (const float*)d_in[3];   // [B,S,2] f32
    const float* W     = (const float*)d_in[4];   // [2H,2]  f32
    const float* bias  = (const float*)d_in[5];   // [2]     f32
    float* out = (float*)d_out;

    k_dots<<<BB * SS, 256>>>(h, W);
    k_scan<<<BB, 256>>>(amask, smask, gum, bias, out);
    k_merge<<<BB * SS, 256>>>(h, out);
}

// round 6
// speedup vs baseline: 1.0535x; 1.0535x over previous
#include <cuda_runtime.h>

// Problem shape (fixed by the bench)
#define BB 8
#define SS 2048
#define HH 2048

// Scratch (no allocations allowed)
__device__ float g_uv[BB * SS * 4];      // per-row dots: h·W[:H,0], h·W[:H,1], h·W[H:,0], h·W[H:,1]
__device__ float g_v[BB * SS];           // per-input-position weight in transform
__device__ int   g_seg_start[BB * SS];   // first input s for output row t
__device__ int   g_seg_len[BB * SS];     // number of input s for output row t
__device__ int   g_new_len[BB];

// ---------------------------------------------------------------------------
// Kernel A (persistent columns): thread tid owns h columns tid*8..tid*8+7 and
// keeps the 32 matching W values in registers; block processes 8 rows.
// L1 traffic is now h-only; kernel should be HBM-bound.
// ---------------------------------------------------------------------------
__global__ void __launch_bounds__(256) k_dots(const float* __restrict__ h,
                                              const float* __restrict__ W) {
    const int tid = threadIdx.x;
    const int warp = tid >> 5, lane = tid & 31;
    const float4* Wp = reinterpret_cast<const float4*>(W);   // W: [2H,2] row-major
    const int q0 = tid * 2;                                  // first h-float4 index

    // W float4 q covers rows 2q,2q+1 (cols 0,1). For h cols j..j+3 we need
    // W float4s j/2, j/2+1. Thread's cols start at j0 = tid*8 -> j0/2 = tid*4.
    const float4 wa0 = __ldg(Wp + tid * 4 + 0);
    const float4 wa1 = __ldg(Wp + tid * 4 + 1);
    const float4 wa2 = __ldg(Wp + tid * 4 + 2);
    const float4 wa3 = __ldg(Wp + tid * 4 + 3);
    const float4 wb0 = __ldg(Wp + 1024 + tid * 4 + 0);       // second half: rows H+j
    const float4 wb1 = __ldg(Wp + 1024 + tid * 4 + 1);
    const float4 wb2 = __ldg(Wp + 1024 + tid * 4 + 2);
    const float4 wb3 = __ldg(Wp + 1024 + tid * 4 + 3);

    __shared__ float red[2][8][4];                           // double-buffered partials

    const int row0 = blockIdx.x * 8;
#pragma unroll
    for (int rr = 0; rr < 8; rr++) {
        const int row = row0 + rr;
        const float4* hp = reinterpret_cast<const float4*>(h) + (size_t)row * (HH / 4);
        const float4 h0 = __ldg(hp + q0);
        const float4 h1 = __ldg(hp + q0 + 1);

        float a0 = h0.x * wa0.x + h0.y * wa0.z + h0.z * wa1.x + h0.w * wa1.z
                 + h1.x * wa2.x + h1.y * wa2.z + h1.z * wa3.x + h1.w * wa3.z;
        float a1 = h0.x * wa0.y + h0.y * wa0.w + h0.z * wa1.y + h0.w * wa1.w
                 + h1.x * wa2.y + h1.y * wa2.w + h1.z * wa3.y + h1.w * wa3.w;
        float c0 = h0.x * wb0.x + h0.y * wb0.z + h0.z * wb1.x + h0.w * wb1.z
                 + h1.x * wb2.x + h1.y * wb2.z + h1.z * wb3.x + h1.w * wb3.z;
        float c1 = h0.x * wb0.y + h0.y * wb0.w + h0.z * wb1.y + h0.w * wb1.w
                 + h1.x * wb2.y + h1.y * wb2.w + h1.z * wb3.y + h1.w * wb3.w;

#pragma unroll
        for (int off = 16; off > 0; off >>= 1) {
            a0 += __shfl_down_sync(0xffffffffu, a0, off);
            a1 += __shfl_down_sync(0xffffffffu, a1, off);
            c0 += __shfl_down_sync(0xffffffffu, c0, off);
            c1 += __shfl_down_sync(0xffffffffu, c1, off);
        }
        const int buf = rr & 1;
        if (lane == 0) {
            red[buf][warp][0] = a0; red[buf][warp][1] = a1;
            red[buf][warp][2] = c0; red[buf][warp][3] = c1;
        }
        __syncthreads();
        if (tid < 4) {
            float s = 0.f;
#pragma unroll
            for (int w = 0; w < 8; w++) s += red[buf][w][tid];
            g_uv[(size_t)row * 4 + tid] = s;
        }
        // next iteration writes the other buffer; the sync inside iteration
        // rr+1 orders the tid<4 reads of buf before its reuse at rr+2.
    }
}

// ---------------------------------------------------------------------------
// Kernel B: per-batch. logits, gumbel-softmax, mm, want, v, prefix scan of inc,
// segment map, and all small outputs. One 256-thread block per batch.
// ---------------------------------------------------------------------------
__global__ void __launch_bounds__(256) k_scan(const int* __restrict__ amask,
                                              const int* __restrict__ smask,
                                              const float* __restrict__ gum,
                                              const float* __restrict__ bias,
                                              float* __restrict__ out) {
    const int b = blockIdx.x;
    const int tid = threadIdx.x;
    const size_t base = (size_t)b * SS;

    __shared__ unsigned char want_sh[SS];
    __shared__ int r_sh[SS];
    __shared__ int part[256];
    __shared__ int cnt_sh[SS];
    __shared__ int sst_sh[SS];
    __shared__ int sh_T;

    // output layout: tuple members concatenated, all fp32
    float* out_mask    = out + (size_t)BB * SS * HH;
    float* out_special = out_mask + (size_t)BB * SS;
    float* out_counts  = out_special + (size_t)BB * SS;
    float* out_mm      = out_counts + (size_t)BB * SS;
    float* out_logits  = out_mm + (size_t)BB * SS * 2;

    // --- T = sum(attention_mask[b]) ---
    if (tid == 0) sh_T = 0;
    __syncthreads();
    {
        int local = 0;
#pragma unroll
        for (int i = 0; i < 8; i++) local += amask[base + tid * 8 + i];
        atomicAdd(&sh_T, local);
    }
    __syncthreads();
    const int T = sh_T;

    const float b0v = __ldg(bias + 0), b1v = __ldg(bias + 1);

    // --- per-position: logits, gumbel-softmax, mm, want, v ---
#pragma unroll
    for (int i = 0; i < 8; i++) {
        const int s = tid * 8 + i;
        float l0, l1;
        if (s < SS - 1) {
            const float* uvA = g_uv + (base + s) * 4;
            const float* uvB = g_uv + (base + s + 1) * 4;
            l0 = uvA[0] + uvB[2] + b0v;
            l1 = uvA[1] + uvB[3] + b1v;
        } else {                                     // zero stub row
            l0 = b0v; l1 = b1v;
        }
        out_logits[(base + s) * 2 + 0] = l0;
        out_logits[(base + s) * 2 + 1] = l1;

        const float z0 = l0 + gum[(base + s) * 2 + 0];
        const float z1 = l1 + gum[(base + s) * 2 + 1];
        const float m = fmaxf(z0, z1);
        const float e0 = expf(z0 - m), e1 = expf(z1 - m);
        const float inv = 1.f / (e0 + e1);
        const float ys0 = e0 * inv, ys1 = e1 * inv;
        const int idx1 = (ys1 > ys0) ? 1 : 0;        // argmax, ties -> 0 (matches jnp)
        float mm0 = ((idx1 == 0 ? 1.f : 0.f) - ys0) + ys0;   // straight-through, exact fp order
        float mm1 = ((idx1 == 1 ? 1.f : 0.f) - ys1) + ys1;
        if (smask[base + s]) { mm0 = 1.f; mm1 = 0.f; }
        const float mf = amask[base + s] ? 1.f : 0.f;
        mm0 *= mf; mm1 *= mf;
        out_mm[(base + s) * 2 + 0] = mm0;
        out_mm[(base + s) * 2 + 1] = mm1;

        const bool want = (mm1 > 0.5f) && (s >= 1) && (s < T - 1);
        want_sh[s] = want ? 1 : 0;
        float v = want ? mm1 : mm0;
        if (s == 0) v = 1.f;
        if (s >= T) v = 0.f;
        g_v[base + s] = v;
    }
    __syncthreads();

    // --- inc + block prefix scan -> r ---
    int incs[8];
    {
        int csum = 0;
#pragma unroll
        for (int i = 0; i < 8; i++) {
            const int s = tid * 8 + i;
            const int w = want_sh[s];
            const int wp = (s > 0) ? want_sh[s - 1] : 0;
            const int inc = (s < T && s >= 1 && !(w && wp)) ? 1 : 0;
            csum += inc;
            incs[i] = csum;                          // local inclusive
        }
        part[tid] = csum;
    }
    __syncthreads();
    for (int off = 1; off < 256; off <<= 1) {
        const int add = (tid >= off) ? part[tid - off] : 0;
        __syncthreads();
        part[tid] += add;
        __syncthreads();
    }
    {
        const int offset = (tid > 0) ? part[tid - 1] : 0;
#pragma unroll
        for (int i = 0; i < 8; i++) r_sh[tid * 8 + i] = offset + incs[i];
    }
    __syncthreads();

    // --- segment map via shared atomics ---
#pragma unroll
    for (int i = 0; i < 8; i++) { cnt_sh[tid * 8 + i] = 0; sst_sh[tid * 8 + i] = 0x7fffffff; }
    __syncthreads();
#pragma unroll
    for (int i = 0; i < 8; i++) {
        const int s = tid * 8 + i;
        if (s < T) {
            const int r = r_sh[s];
            atomicAdd(&cnt_sh[r], 1);
            atomicMin(&sst_sh[r], s);
        }
    }
    __syncthreads();

    const int nl = r_sh[SS - 1] + 1;                 // matches reference r[:, -1] + 1
#pragma unroll
    for (int i = 0; i < 8; i++) {
        const int t = tid * 8 + i;
        out_mask[base + t]    = (t < nl) ? 1.f : 0.f;
        out_special[base + t] = (t == 0 || t == nl - 1) ? 1.f : 0.f;
        out_counts[base + t]  = (float)cnt_sh[t];
        g_seg_start[base + t] = sst_sh[t];
        g_seg_len[base + t]   = cnt_sh[t];
    }
    if (tid == 0) g_new_len[b] = nl;
}

// ---------------------------------------------------------------------------
// Kernel C: merged_hidden[b,t,:] = sum over the run of v[s]*h[b,s,:].
// One 128-thread block per output row, 4 float4s per thread (MLP=4);
// zeros for t >= new_len.
// ---------------------------------------------------------------------------
__global__ void __launch_bounds__(128) k_merge(const float* __restrict__ h,
                                               float* __restrict__ out) {
    const int row = blockIdx.x;                      // b*SS + t
    const int b = row >> 11;                         // / SS
    const int t = row & (SS - 1);
    const int tid = threadIdx.x;

    float4 acc0 = make_float4(0.f, 0.f, 0.f, 0.f);
    float4 acc1 = make_float4(0.f, 0.f, 0.f, 0.f);
    float4 acc2 = make_float4(0.f, 0.f, 0.f, 0.f);
    float4 acc3 = make_float4(0.f, 0.f, 0.f, 0.f);

    if (t < g_new_len[b]) {
        const int s0 = g_seg_start[row];
        const int L  = g_seg_len[row];
        for (int i = 0; i < L; i++) {
            const size_t srow = (size_t)b * SS + s0 + i;
            const float w = __ldg(g_v + srow);
            const float4* hr = reinterpret_cast<const float4*>(h) + srow * (HH / 4);
            const float4 h0 = __ldg(hr + tid);
            const float4 h1 = __ldg(hr + tid + 128);
            const float4 h2 = __ldg(hr + tid + 256);
            const float4 h3 = __ldg(hr + tid + 384);
            acc0.x += w * h0.x; acc0.y += w * h0.y; acc0.z += w * h0.z; acc0.w += w * h0.w;
            acc1.x += w * h1.x; acc1.y += w * h1.y; acc1.z += w * h1.z; acc1.w += w * h1.w;
            acc2.x += w * h2.x; acc2.y += w * h2.y; acc2.z += w * h2.z; acc2.w += w * h2.w;
            acc3.x += w * h3.x; acc3.y += w * h3.y; acc3.z += w * h3.z; acc3.w += w * h3.w;
        }
    }
    float4* orow = reinterpret_cast<float4*>(out) + (size_t)row * (HH / 4);
    orow[tid]       = acc0;
    orow[tid + 128] = acc1;
    orow[tid + 256] = acc2;
    orow[tid + 384] = acc3;
}

// ---------------------------------------------------------------------------
extern "C" void kernel_launch(void* const* d_in, const int* in_sizes, int n_in,
                              void* d_out, int out_size) {
    const float* h     = (const float*)d_in[0];   // [B,S,H] f32
    const int*   amask = (const int*)d_in[1];     // [B,S]   i32
    const int*   smask = (const int*)d_in[2];     // [B,S]   i32
    const float* gum   = (const float*)d_in[3];   // [B,S,2] f32
    const float* W     = (const float*)d_in[4];   // [2H,2]  f32
    const float* bias  = (const float*)d_in[5];   // [2]     f32
    float* out = (float*)d_out;

    k_dots<<<(BB * SS) / 8, 256>>>(h, W);
    k_scan<<<BB, 256>>>(amask, smask, gum, bias, out);
    k_merge<<<BB * SS, 128>>>(h, out);
}

// round 7
// speedup vs baseline: 1.1903x; 1.1298x over previous
#include <cuda_runtime.h>

// Problem shape (fixed by the bench)
#define BB 8
#define SS 2048
#define HH 2048

// Scratch (no allocations allowed)
__device__ float g_uv[BB * SS * 4];      // per-row dots: h·W[:H,0], h·W[:H,1], h·W[H:,0], h·W[H:,1]
__device__ float g_v[BB * SS];           // per-input-position weight in transform
__device__ int   g_seg_start[BB * SS];   // first input s for output row t
__device__ int   g_seg_len[BB * SS];     // number of input s for output row t
__device__ int   g_new_len[BB];

// ---------------------------------------------------------------------------
// Kernel A: thread tid owns h columns tid*8..tid*8+7 with its 32 W values in
// registers. Block processes an 8-row tile with software prefetch and a SINGLE
// barrier per tile (warp partials land in per-row smem slots; 32 threads do
// the final cross-warp reduction). Removes the per-row lockstep that made the
// previous version latency-bound.
// ---------------------------------------------------------------------------
__global__ void __launch_bounds__(256) k_dots(const float* __restrict__ h,
                                              const float* __restrict__ W) {
    const int tid = threadIdx.x;
    const int warp = tid >> 5, lane = tid & 31;
    const float4* Wp = reinterpret_cast<const float4*>(W);   // W: [2H,2] row-major
    const int q0 = tid * 2;                                  // first h-float4 index

    const float4 wa0 = __ldg(Wp + tid * 4 + 0);
    const float4 wa1 = __ldg(Wp + tid * 4 + 1);
    const float4 wa2 = __ldg(Wp + tid * 4 + 2);
    const float4 wa3 = __ldg(Wp + tid * 4 + 3);
    const float4 wb0 = __ldg(Wp + 1024 + tid * 4 + 0);       // second half: rows H+j
    const float4 wb1 = __ldg(Wp + 1024 + tid * 4 + 1);
    const float4 wb2 = __ldg(Wp + 1024 + tid * 4 + 2);
    const float4 wb3 = __ldg(Wp + 1024 + tid * 4 + 3);

    __shared__ float red[8][8][4];                           // [row][warp][comp]

    const int row0 = blockIdx.x * 8;
    const float4* hp = reinterpret_cast<const float4*>(h) + (size_t)row0 * (HH / 4);

    float4 h0 = __ldg(hp + q0);
    float4 h1 = __ldg(hp + q0 + 1);

#pragma unroll
    for (int rr = 0; rr < 8; rr++) {
        float4 n0, n1;
        if (rr < 7) {                                        // prefetch next row
            const float4* np = hp + (size_t)(rr + 1) * (HH / 4);
            n0 = __ldg(np + q0);
            n1 = __ldg(np + q0 + 1);
        }

        float a0 = h0.x * wa0.x + h0.y * wa0.z + h0.z * wa1.x + h0.w * wa1.z
                 + h1.x * wa2.x + h1.y * wa2.z + h1.z * wa3.x + h1.w * wa3.z;
        float a1 = h0.x * wa0.y + h0.y * wa0.w + h0.z * wa1.y + h0.w * wa1.w
                 + h1.x * wa2.y + h1.y * wa2.w + h1.z * wa3.y + h1.w * wa3.w;
        float c0 = h0.x * wb0.x + h0.y * wb0.z + h0.z * wb1.x + h0.w * wb1.z
                 + h1.x * wb2.x + h1.y * wb2.z + h1.z * wb3.x + h1.w * wb3.z;
        float c1 = h0.x * wb0.y + h0.y * wb0.w + h0.z * wb1.y + h0.w * wb1.w
                 + h1.x * wb2.y + h1.y * wb2.w + h1.z * wb3.y + h1.w * wb3.w;

#pragma unroll
        for (int off = 16; off > 0; off >>= 1) {
            a0 += __shfl_down_sync(0xffffffffu, a0, off);
            a1 += __shfl_down_sync(0xffffffffu, a1, off);
            c0 += __shfl_down_sync(0xffffffffu, c0, off);
            c1 += __shfl_down_sync(0xffffffffu, c1, off);
        }
        if (lane == 0) {
            red[rr][warp][0] = a0; red[rr][warp][1] = a1;
            red[rr][warp][2] = c0; red[rr][warp][3] = c1;
        }
        if (rr < 7) { h0 = n0; h1 = n1; }
    }
    __syncthreads();                                         // ONE barrier per tile

    if (tid < 32) {
        const int rr = tid >> 2, c = tid & 3;
        float s = 0.f;
#pragma unroll
        for (int w = 0; w < 8; w++) s += red[rr][w][c];
        g_uv[(size_t)(row0 + rr) * 4 + c] = s;
    }
}

// ---------------------------------------------------------------------------
// Kernel B: per-batch. logits, gumbel-softmax, mm, want, v, prefix scan of inc,
// segment map, and all small outputs. One 256-thread block per batch.
// ---------------------------------------------------------------------------
__global__ void __launch_bounds__(256) k_scan(const int* __restrict__ amask,
                                              const int* __restrict__ smask,
                                              const float* __restrict__ gum,
                                              const float* __restrict__ bias,
                                              float* __restrict__ out) {
    const int b = blockIdx.x;
    const int tid = threadIdx.x;
    const size_t base = (size_t)b * SS;

    __shared__ unsigned char want_sh[SS];
    __shared__ int r_sh[SS];
    __shared__ int part[256];
    __shared__ int cnt_sh[SS];
    __shared__ int sst_sh[SS];
    __shared__ int sh_T;

    // output layout: tuple members concatenated, all fp32
    float* out_mask    = out + (size_t)BB * SS * HH;
    float* out_special = out_mask + (size_t)BB * SS;
    float* out_counts  = out_special + (size_t)BB * SS;
    float* out_mm      = out_counts + (size_t)BB * SS;
    float* out_logits  = out_mm + (size_t)BB * SS * 2;

    // --- T = sum(attention_mask[b]) ---
    if (tid == 0) sh_T = 0;
    __syncthreads();
    {
        int local = 0;
#pragma unroll
        for (int i = 0; i < 8; i++) local += amask[base + tid * 8 + i];
        atomicAdd(&sh_T, local);
    }
    __syncthreads();
    const int T = sh_T;

    const float b0v = __ldg(bias + 0), b1v = __ldg(bias + 1);

    // --- per-position: logits, gumbel-softmax, mm, want, v ---
#pragma unroll
    for (int i = 0; i < 8; i++) {
        const int s = tid * 8 + i;
        float l0, l1;
        if (s < SS - 1) {
            const float* uvA = g_uv + (base + s) * 4;
            const float* uvB = g_uv + (base + s + 1) * 4;
            l0 = uvA[0] + uvB[2] + b0v;
            l1 = uvA[1] + uvB[3] + b1v;
        } else {                                     // zero stub row
            l0 = b0v; l1 = b1v;
        }
        out_logits[(base + s) * 2 + 0] = l0;
        out_logits[(base + s) * 2 + 1] = l1;

        const float z0 = l0 + gum[(base + s) * 2 + 0];
        const float z1 = l1 + gum[(base + s) * 2 + 1];
        const float m = fmaxf(z0, z1);
        const float e0 = expf(z0 - m), e1 = expf(z1 - m);
        const float inv = 1.f / (e0 + e1);
        const float ys0 = e0 * inv, ys1 = e1 * inv;
        const int idx1 = (ys1 > ys0) ? 1 : 0;        // argmax, ties -> 0 (matches jnp)
        float mm0 = ((idx1 == 0 ? 1.f : 0.f) - ys0) + ys0;   // straight-through, exact fp order
        float mm1 = ((idx1 == 1 ? 1.f : 0.f) - ys1) + ys1;
        if (smask[base + s]) { mm0 = 1.f; mm1 = 0.f; }
        const float mf = amask[base + s] ? 1.f : 0.f;
        mm0 *= mf; mm1 *= mf;
        out_mm[(base + s) * 2 + 0] = mm0;
        out_mm[(base + s) * 2 + 1] = mm1;

        const bool want = (mm1 > 0.5f) && (s >= 1) && (s < T - 1);
        want_sh[s] = want ? 1 : 0;
        float v = want ? mm1 : mm0;
        if (s == 0) v = 1.f;
        if (s >= T) v = 0.f;
        g_v[base + s] = v;
    }
    __syncthreads();

    // --- inc + block prefix scan -> r ---
    int incs[8];
    {
        int csum = 0;
#pragma unroll
        for (int i = 0; i < 8; i++) {
            const int s = tid * 8 + i;
            const int w = want_sh[s];
            const int wp = (s > 0) ? want_sh[s - 1] : 0;
            const int inc = (s < T && s >= 1 && !(w && wp)) ? 1 : 0;
            csum += inc;
            incs[i] = csum;                          // local inclusive
        }
        part[tid] = csum;
    }
    __syncthreads();
    for (int off = 1; off < 256; off <<= 1) {
        const int add = (tid >= off) ? part[tid - off] : 0;
        __syncthreads();
        part[tid] += add;
        __syncthreads();
    }
    {
        const int offset = (tid > 0) ? part[tid - 1] : 0;
#pragma unroll
        for (int i = 0; i < 8; i++) r_sh[tid * 8 + i] = offset + incs[i];
    }
    __syncthreads();

    // --- segment map via shared atomics ---
#pragma unroll
    for (int i = 0; i < 8; i++) { cnt_sh[tid * 8 + i] = 0; sst_sh[tid * 8 + i] = 0x7fffffff; }
    __syncthreads();
#pragma unroll
    for (int i = 0; i < 8; i++) {
        const int s = tid * 8 + i;
        if (s < T) {
            const int r = r_sh[s];
            atomicAdd(&cnt_sh[r], 1);
            atomicMin(&sst_sh[r], s);
        }
    }
    __syncthreads();

    const int nl = r_sh[SS - 1] + 1;                 // matches reference r[:, -1] + 1
#pragma unroll
    for (int i = 0; i < 8; i++) {
        const int t = tid * 8 + i;
        out_mask[base + t]    = (t < nl) ? 1.f : 0.f;
        out_special[base + t] = (t == 0 || t == nl - 1) ? 1.f : 0.f;
        out_counts[base + t]  = (float)cnt_sh[t];
        g_seg_start[base + t] = sst_sh[t];
        g_seg_len[base + t]   = cnt_sh[t];
    }
    if (tid == 0) g_new_len[b] = nl;
}

// ---------------------------------------------------------------------------
// Kernel C: merged_hidden[b,t,:] = sum over the run of v[s]*h[b,s,:].
// One 128-thread block per output row, 4 float4s per thread (MLP=4).
// Blocks traverse rows in DESCENDING order so the h rows still resident in L2
// from k_dots' ascending stream are re-read while hot (ascending order would
// LRU-thrash). Output stores use __stcs (evict-first) so the 134MB of writes
// don't evict the h working set from L2.
// ---------------------------------------------------------------------------
__global__ void __launch_bounds__(128) k_merge(const float* __restrict__ h,
                                               float* __restrict__ out) {
    const int row = (BB * SS - 1) - blockIdx.x;      // descending traversal
    const int b = row >> 11;                         // / SS
    const int t = row & (SS - 1);
    const int tid = threadIdx.x;

    float4 acc0 = make_float4(0.f, 0.f, 0.f, 0.f);
    float4 acc1 = make_float4(0.f, 0.f, 0.f, 0.f);
    float4 acc2 = make_float4(0.f, 0.f, 0.f, 0.f);
    float4 acc3 = make_float4(0.f, 0.f, 0.f, 0.f);

    if (t < g_new_len[b]) {
        const int s0 = g_seg_start[row];
        const int L  = g_seg_len[row];
        for (int i = 0; i < L; i++) {
            const size_t srow = (size_t)b * SS + s0 + i;
            const float w = __ldg(g_v + srow);
            const float4* hr = reinterpret_cast<const float4*>(h) + srow * (HH / 4);
            const float4 h0 = __ldg(hr + tid);
            const float4 h1 = __ldg(hr + tid + 128);
            const float4 h2 = __ldg(hr + tid + 256);
            const float4 h3 = __ldg(hr + tid + 384);
            acc0.x += w * h0.x; acc0.y += w * h0.y; acc0.z += w * h0.z; acc0.w += w * h0.w;
            acc1.x += w * h1.x; acc1.y += w * h1.y; acc1.z += w * h1.z; acc1.w += w * h1.w;
            acc2.x += w * h2.x; acc2.y += w * h2.y; acc2.z += w * h2.z; acc2.w += w * h2.w;
            acc3.x += w * h3.x; acc3.y += w * h3.y; acc3.z += w * h3.z; acc3.w += w * h3.w;
        }
    }
    float4* orow = reinterpret_cast<float4*>(out) + (size_t)row * (HH / 4);
    __stcs(orow + tid,       acc0);
    __stcs(orow + tid + 128, acc1);
    __stcs(orow + tid + 256, acc2);
    __stcs(orow + tid + 384, acc3);
}

// ---------------------------------------------------------------------------
extern "C" void kernel_launch(void* const* d_in, const int* in_sizes, int n_in,
                              void* d_out, int out_size) {
    const float* h     = (const float*)d_in[0];   // [B,S,H] f32
    const int*   amask = (const int*)d_in[1];     // [B,S]   i32
    const int*   smask = (const int*)d_in[2];     // [B,S]   i32
    const float* gum   = (const float*)d_in[3];   // [B,S,2] f32
    const float* W     = (const float*)d_in[4];   // [2H,2]  f32
    const float* bias  = (const float*)d_in[5];   // [2]     f32
    float* out = (float*)d_out;

    k_dots<<<(BB * SS) / 8, 256>>>(h, W);
    k_scan<<<BB, 256>>>(amask, smask, gum, bias, out);
    k_merge<<<BB * SS, 128>>>(h, out);
}